// round 15
// baseline (speedup 1.0000x reference)
#include <cuda_runtime.h>
#include <cuda_fp16.h>
#include <cstdint>

#define MAXN 100000
#define MAXE 3200000
#define CIN 128
#define H1 50
#define H1P 52            // fp32 row stride for ho1 (gemm2 input)
#define H2 40
#define H2P 44
#define NEG_SLOPE 0.2f
#define SCAN_CHUNK 1024
#define R1U 32            // layer1 h row: 32 uints = 64 fp16 = 128B (feat 0..24, as@25)
#define R2U 24            // layer2 h row: 24 uints = 48 fp16 =  96B (feat 0..19, as@20)

// -------- scratch (device globals; no runtime allocation allowed) ----------
__device__ unsigned g_h1u[(size_t)MAXN * R1U];
__device__ unsigned g_h2u[(size_t)MAXN * R2U];
__device__ float    g_ho1[(size_t)MAXN * H1P];
__device__ float    g_ad1[MAXN], g_ad2[MAXN];
__device__ int      g_deg[MAXN + 4];
__device__ int      g_off[MAXN + 1];
__device__ int      g_rank[MAXE + 4];           // per-edge rank within its dst segment
__device__ int      g_part[1100];               // lookback mailboxes (0 = not ready)
__device__ int      g_csr[MAXE + MAXN];
__device__ int      g_is64;
__device__ int      g_scan_done;                // completed scan blocks

// -------- f32x2 helpers (Blackwell packed fp32, PTX-only) --------
__device__ __forceinline__ unsigned long long splat2(float v) {
    unsigned long long r; unsigned b = __float_as_uint(v);
    asm("mov.b64 %0, {%1, %1};" : "=l"(r) : "r"(b));
    return r;
}
__device__ __forceinline__ void ffma2(unsigned long long& acc, unsigned long long a, unsigned long long b) {
    asm("fma.rn.f32x2 %0, %1, %2, %0;" : "+l"(acc) : "l"(a), "l"(b));
}
__device__ __forceinline__ float2 unpack2(unsigned long long v) {
    unsigned lo, hi;
    asm("mov.b64 {%0, %1}, %2;" : "=r"(lo), "=r"(hi) : "l"(v));
    return make_float2(__uint_as_float(lo), __uint_as_float(hi));
}

// ---------------- k1: block 0 = dtype probe + flag clears; rest deg init ----
__global__ void init_k(const uint2* __restrict__ ei8, long long twoE,
                       int* __restrict__ deg, int* __restrict__ part, int n) {
    if (blockIdx.x == 0) {
        __shared__ int anyHi;
        if (threadIdx.x == 0) anyHi = 0;
        __syncthreads();
        long long K = twoE < 1024 ? twoE : 1024;
        for (long long i = threadIdx.x; i < K; i += blockDim.x) {
            uint2 v = ei8[i];
            if (v.y != 0u) anyHi = 1;   // int32 data: high half = next index, ~never all-zero
        }
        __syncthreads();
        if (threadIdx.x == 0) { g_is64 = anyHi ? 0 : 1; g_scan_done = 0; }
        for (int i = threadIdx.x; i < 1100; i += blockDim.x) part[i] = 0;
    } else {
        int i = (blockIdx.x - 1) * 128 + threadIdx.x;
        if (i < n) deg[i] = 1;          // slot 0 of each segment = self-loop
    }
}

// ---------------- k2 (fused): gemm1 | degree count+rank | ei-cast tail ------
__global__ void fused1_k(const float* __restrict__ x, const float* __restrict__ W,
                         const float* __restrict__ att_s, const float* __restrict__ att_d,
                         int n, unsigned* __restrict__ hrows, float* __restrict__ ad_o,
                         const void* __restrict__ ei, long long E,
                         int* __restrict__ deg, int* __restrict__ rank,
                         int NB1, int CB, float* __restrict__ otail) {
    int bid = blockIdx.x;
    int tid = threadIdx.x;
    if (bid < NB1) {
        __shared__ float Ws[CIN * H1P];
        __shared__ float xs[128 * 17];
        __shared__ float sa[H1], sd[H1];
        for (int j = tid; j < CIN * H1; j += 128) {
            int k = j / H1, f = j - k * H1;
            Ws[k * H1P + f] = W[j];
        }
        if (tid < H1) { sa[tid] = att_s[tid]; sd[tid] = att_d[tid]; }

        int node = bid * 128 + tid;
        unsigned long long acc2[25];
#pragma unroll
        for (int i = 0; i < 25; i++) acc2[i] = 0ull;

        const float4* x4 = (const float4*)x;
        for (int k0 = 0; k0 < CIN; k0 += 16) {
            __syncthreads();
#pragma unroll
            for (int j = tid; j < 512; j += 128) {
                int nd = j >> 2, c = j & 3;
                int gn = bid * 128 + nd;
                float4 v = make_float4(0.f, 0.f, 0.f, 0.f);
                if (gn < n) v = x4[(size_t)gn * (CIN / 4) + (k0 >> 2) + c];
                float* p = &xs[nd * 17 + c * 4];
                p[0] = v.x; p[1] = v.y; p[2] = v.z; p[3] = v.w;
            }
            __syncthreads();
#pragma unroll
            for (int kk = 0; kk < 16; kk++) {
                unsigned long long xv2 = splat2(xs[tid * 17 + kk]);
                const unsigned long long* wr = (const unsigned long long*)&Ws[(k0 + kk) * H1P];
#pragma unroll
                for (int fp = 0; fp < 25; fp++) ffma2(acc2[fp], xv2, wr[fp]);
            }
        }
        if (node < n) {
            float s = 0.f, d = 0.f;
            unsigned* hr = hrows + (size_t)node * R1U;
#pragma unroll
            for (int fp = 0; fp < 25; fp++) {
                float2 v = unpack2(acc2[fp]);
                s += v.x * sa[2 * fp] + v.y * sa[2 * fp + 1];
                d += v.x * sd[2 * fp] + v.y * sd[2 * fp + 1];
                __half2 hh = __floats2half2_rn(v.x, v.y);
                hr[fp] = *(unsigned*)&hh;
            }
            hr[25] = __float_as_uint(s);        // embedded fp32 a_src
#pragma unroll
            for (int q = 26; q < R1U; q++) hr[q] = 0u;
            ad_o[node] = d;
        }
    } else if (bid < NB1 + CB) {
        // degree count + rank capture: 4 edges/thread
        long long i0 = (long long)(bid - NB1) * 512 + tid * 4;
        if (i0 < E) {
            int cnt = (E - i0 >= 4) ? 4 : (int)(E - i0);
            int d[4], rk[4];
            if (g_is64) {
                const long long* p = (const long long*)ei + E;   // dst row
                for (int u = 0; u < cnt; u++) d[u] = (int)p[i0 + u];
            } else {
                const int* p = (const int*)ei + E;
                if (cnt == 4) {
                    int4 q = *(const int4*)(p + i0);
                    d[0] = q.x; d[1] = q.y; d[2] = q.z; d[3] = q.w;
                } else {
                    for (int u = 0; u < cnt; u++) d[u] = p[i0 + u];
                }
            }
            for (int u = 0; u < cnt; u++) {
                int dd = d[u];
                if ((unsigned)dd >= (unsigned)n) dd = 0;
                rk[u] = atomicAdd(deg + dd, 1);              // rank >= 1 (0 = self-loop)
            }
            if (cnt == 4) *(int4*)(rank + i0) = make_int4(rk[0], rk[1], rk[2], rk[3]);
            else for (int u = 0; u < cnt; u++) rank[i0 + u] = rk[u];
        }
    } else {
        // ei-cast tail: 4 elems/thread
        long long twoE = 2 * E;
        long long j0 = (long long)(bid - NB1 - CB) * 512 + tid * 4;
        if (j0 < twoE) {
            float o[4]; int cnt = (twoE - j0 >= 4) ? 4 : (int)(twoE - j0);
            if (g_is64) {
                const long long* p = (const long long*)ei;
                for (int u = 0; u < cnt; u++) o[u] = (float)p[j0 + u];
            } else {
                const int* p = (const int*)ei;
                if (cnt == 4) {
                    int4 q = *(const int4*)(p + j0);
                    o[0] = (float)q.x; o[1] = (float)q.y; o[2] = (float)q.z; o[3] = (float)q.w;
                } else {
                    for (int u = 0; u < cnt; u++) o[u] = (float)p[j0 + u];
                }
            }
            if (cnt == 4) *(float4*)(otail + j0) = make_float4(o[0], o[1], o[2], o[3]);
            else for (int u = 0; u < cnt; u++) otail[j0 + u] = o[u];
        }
    }
}

// ---------------- k3 (merged): scan (lookback) + spin-wait scatter ----------
// blocks [0, NSCAN)            : chunk scan -> off; threadfence; bump g_scan_done
// blocks [NSCAN, NSCAN+SB)     : spin until scan done, then edge scatter
// blocks [NSCAN+SB, ..)        : spin, then self-loop scatter (slot 0)
// Safe: scan blocks are in wave 1 (grid >> 148 but lowest bids schedule first)
// and wait on nothing; all other blocks wait only on them.
__global__ void scan_scatter_k(const int* __restrict__ deg, int* __restrict__ part,
                               int* __restrict__ off, int n, int total,
                               const void* __restrict__ ei, long long E,
                               const int* __restrict__ rank, int* __restrict__ csr,
                               int NSCAN, int SB) {
    int bid = blockIdx.x, t = threadIdx.x;
    if (bid < NSCAN) {
        __shared__ int ts[256];
        __shared__ int sbase;
        int base = bid * SCAN_CHUNK;
        int i0 = base + t * 4;
        int v0 = 0, v1 = 0, v2 = 0, v3 = 0;
        if (i0 + 3 < n) {
            int4 q = *(const int4*)(deg + i0);
            v0 = q.x; v1 = q.y; v2 = q.z; v3 = q.w;
        } else {
            if (i0 + 0 < n) v0 = deg[i0 + 0];
            if (i0 + 1 < n) v1 = deg[i0 + 1];
            if (i0 + 2 < n) v2 = deg[i0 + 2];
            if (i0 + 3 < n) v3 = deg[i0 + 3];
        }
        ts[t] = v0 + v1 + v2 + v3;
        __syncthreads();
#pragma unroll
        for (int d = 1; d < 256; d <<= 1) {
            int v = (t >= d) ? ts[t - d] : 0;
            __syncthreads();
            ts[t] += v;
            __syncthreads();
        }
        if (t == 0) atomicExch(part + bid, ts[255]);   // chunk total >= 1
        if (t < 32) {
            int sum = 0;
            volatile int* vp = part;
            for (int i = t; i < bid; i += 32) {
                int v;
                do { v = vp[i]; } while (v == 0);
                sum += v;
            }
#pragma unroll
            for (int o = 16; o > 0; o >>= 1) sum += __shfl_xor_sync(0xffffffffu, sum, o);
            if (t == 0) sbase = sum;
        }
        __syncthreads();
        int run = sbase + (t ? ts[t - 1] : 0);
        if (i0 + 0 < n) { off[i0 + 0] = run; run += v0; }
        if (i0 + 1 < n) { off[i0 + 1] = run; run += v1; }
        if (i0 + 2 < n) { off[i0 + 2] = run; run += v2; }
        if (i0 + 3 < n) { off[i0 + 3] = run; run += v3; }
        if (bid == 0 && t == 0) off[n] = total;
        // publish: all off writes visible before counter bump
        __syncthreads();
        if (t == 0) {
            __threadfence();
            atomicAdd(&g_scan_done, 1);
        }
        return;
    }

    // ---- non-scan blocks: wait for the full off[] array ----
    if (t == 0) {
        while (*(volatile int*)&g_scan_done < NSCAN) __nanosleep(64);
    }
    __syncthreads();
    __threadfence();                    // order subsequent off loads after the flag

    int sbid = bid - NSCAN;
    if (sbid < SB) {
        long long i0 = (long long)sbid * 1024 + t * 4;
        if (i0 >= E) return;
        int cnt = (E - i0 >= 4) ? 4 : (int)(E - i0);
        int s[4], d[4], rk[4];
        if (g_is64) {
            const long long* ps = (const long long*)ei;
            const long long* pd = ps + E;
            for (int u = 0; u < cnt; u++) { s[u] = (int)ps[i0 + u]; d[u] = (int)pd[i0 + u]; }
        } else {
            const int* ps = (const int*)ei;
            const int* pd = ps + E;
            if (cnt == 4) {
                int4 qs = *(const int4*)(ps + i0);
                int4 qd = *(const int4*)(pd + i0);
                s[0] = qs.x; s[1] = qs.y; s[2] = qs.z; s[3] = qs.w;
                d[0] = qd.x; d[1] = qd.y; d[2] = qd.z; d[3] = qd.w;
            } else {
                for (int u = 0; u < cnt; u++) { s[u] = ps[i0 + u]; d[u] = pd[i0 + u]; }
            }
        }
        if (cnt == 4) {
            int4 qr = *(const int4*)(rank + i0);
            rk[0] = qr.x; rk[1] = qr.y; rk[2] = qr.z; rk[3] = qr.w;
        } else {
            for (int u = 0; u < cnt; u++) rk[u] = rank[i0 + u];
        }
        for (int u = 0; u < cnt; u++) {
            int ss = s[u], dd = d[u];
            if ((unsigned)ss >= (unsigned)n) ss = 0;
            if ((unsigned)dd >= (unsigned)n) dd = 0;
            csr[off[dd] + rk[u]] = ss;
        }
    } else {
        int v0 = (sbid - SB) * 1024 + t * 4;
#pragma unroll
        for (int u = 0; u < 4; u++) {
            int v = v0 + u;
            if (v < n) csr[off[v]] = v;             // self-loop at slot 0
        }
    }
}

// ---------------- agg core: one warp per dst node (serial tail) --------------
template <int STRIDE_U, int AS_LANE>
__device__ __forceinline__ void agg_core(const int* __restrict__ off, const int* __restrict__ csr,
                                         const float* __restrict__ ad, const unsigned* __restrict__ hrows,
                                         int warp, int lane, float& ax, float& ay, float& z) {
    int beg = __ldg(off + warp), end = __ldg(off + warp + 1);
    float adv = __ldg(ad + warp);
    ax = 0.f; ay = 0.f; z = 0.f;
    bool ldok = (STRIDE_U == 32) || (lane < STRIDE_U);

    int p = beg;
    for (; p + 8 <= end; p += 8) {
        int sv = (lane < 8) ? __ldg(csr + p + lane) : 0;   // 1 coalesced request
        int s[8]; unsigned r[8];
#pragma unroll
        for (int u = 0; u < 8; u++) s[u] = __shfl_sync(0xffffffffu, sv, u);
#pragma unroll
        for (int u = 0; u < 8; u++)
            r[u] = ldok ? __ldg(hrows + (size_t)s[u] * STRIDE_U + lane) : 0u;
#pragma unroll
        for (int u = 0; u < 8; u++) {
            float asv = __shfl_sync(0xffffffffu, __uint_as_float(r[u]), AS_LANE);
            float e = asv + adv;
            e = e > 0.f ? e : NEG_SLOPE * e;
            float w = __expf(e);
            float2 hv = __half22float2(*(__half2*)&r[u]);
            z += w; ax += w * hv.x; ay += w * hv.y;
        }
    }
    for (; p < end; p++) {
        int s = __ldg(csr + p);
        unsigned r = ldok ? __ldg(hrows + (size_t)s * STRIDE_U + lane) : 0u;
        float asv = __shfl_sync(0xffffffffu, __uint_as_float(r), AS_LANE);
        float e = asv + adv;
        e = e > 0.f ? e : NEG_SLOPE * e;
        float w = __expf(e);
        float2 hv = __half22float2(*(__half2*)&r);
        z += w; ax += w * hv.x; ay += w * hv.y;
    }
}

// ---------------- agg layer1 -> fp32 ho1 rows --------------------------------
__global__ void agg1_k(const int* __restrict__ off, const int* __restrict__ csr,
                       const float* __restrict__ ad, const unsigned* __restrict__ hrows,
                       const float* __restrict__ bias, int n, float* __restrict__ out) {
    int warp = (blockIdx.x * blockDim.x + threadIdx.x) >> 5;
    int lane = threadIdx.x & 31;
    if (warp >= n) return;
    float ax, ay, z;
    agg_core<R1U, 25>(off, csr, ad, hrows, warp, lane, ax, ay, z);
    float inv = 1.f / z;                        // z >= exp(self-loop) > 0
    if (lane < 25) {
        float2 b = __ldg((const float2*)bias + lane);
        float vx = ax * inv + b.x;
        float vy = ay * inv + b.y;
        float2 o;
        o.x = vx > 0.f ? vx : 0.f;
        o.y = vy > 0.f ? vy : 0.f;
        *(float2*)(out + (size_t)warp * H1P + 2 * lane) = o;
    }
}

// ---------------- GEMM2: h2 = ho1 @ W2 (50->40) -> fp16 rows ----------------
__global__ void gemm2_k(const float* __restrict__ hin, const float* __restrict__ W,
                        const float* __restrict__ att_s, const float* __restrict__ att_d,
                        int n, unsigned* __restrict__ hrows, float* __restrict__ ad_o) {
    __shared__ float Ws[H1 * H2P];
    __shared__ float xs[128 * 53];
    __shared__ float sa[H2], sd[H2];
    int tid = threadIdx.x;
    for (int j = tid; j < H1 * H2; j += 128) {
        int k = j / H2, f = j - k * H2;
        Ws[k * H2P + f] = W[j];
    }
    if (tid < H2) { sa[tid] = att_s[tid]; sd[tid] = att_d[tid]; }

    const float4* hin4 = (const float4*)hin;
#pragma unroll
    for (int j = tid; j < 128 * 13; j += 128) {
        int nd = j / 13, q = j - nd * 13;
        int gn = blockIdx.x * 128 + nd;
        float4 v = make_float4(0.f, 0.f, 0.f, 0.f);
        if (gn < n) v = hin4[(size_t)gn * 13 + q];
        float* p = &xs[nd * 53 + q * 4];
        p[0] = v.x; p[1] = v.y; p[2] = v.z; p[3] = v.w;
    }
    __syncthreads();

    int node = blockIdx.x * 128 + tid;
    unsigned long long acc2[20];
#pragma unroll
    for (int i = 0; i < 20; i++) acc2[i] = 0ull;
#pragma unroll 2
    for (int k = 0; k < H1; k++) {
        unsigned long long xv2 = splat2(xs[tid * 53 + k]);
        const unsigned long long* wr = (const unsigned long long*)&Ws[k * H2P];
#pragma unroll
        for (int fp = 0; fp < 20; fp++) ffma2(acc2[fp], xv2, wr[fp]);
    }
    if (node < n) {
        float s = 0.f, d = 0.f;
        unsigned* hr = hrows + (size_t)node * R2U;
#pragma unroll
        for (int fp = 0; fp < 20; fp++) {
            float2 v = unpack2(acc2[fp]);
            s += v.x * sa[2 * fp] + v.y * sa[2 * fp + 1];
            d += v.x * sd[2 * fp] + v.y * sd[2 * fp + 1];
            __half2 hh = __floats2half2_rn(v.x, v.y);
            hr[fp] = *(unsigned*)&hh;
        }
        hr[20] = __float_as_uint(s);
        hr[21] = 0u; hr[22] = 0u; hr[23] = 0u;
        ad_o[node] = d;
    }
}

// ---------------- agg layer2 -> d_out ----------------------------------------
__global__ void agg2_k(const int* __restrict__ off, const int* __restrict__ csr,
                       const float* __restrict__ ad, const unsigned* __restrict__ hrows,
                       const float* __restrict__ bias, int n, float* __restrict__ out) {
    int warp = (blockIdx.x * blockDim.x + threadIdx.x) >> 5;
    int lane = threadIdx.x & 31;
    if (warp >= n) return;
    float ax, ay, z;
    agg_core<R2U, 20>(off, csr, ad, hrows, warp, lane, ax, ay, z);
    float inv = 1.f / z;
    if (lane < 20) {
        float2 b = __ldg((const float2*)bias + lane);
        float vx = ax * inv + b.x;
        float vy = ay * inv + b.y;
        float2 o;
        o.x = vx > 0.f ? vx : 0.f;
        o.y = vy > 0.f ? vy : 0.f;
        *(float2*)(out + (size_t)warp * H2 + 2 * lane) = o;
    }
}

extern "C" void kernel_launch(void* const* d_in, const int* in_sizes, int n_in,
                              void* d_out, int out_size) {
    const float* x    = (const float*)d_in[0];
    const void*  ei   = d_in[1];
    const float* W1   = (const float*)d_in[2];
    const float* as1w = (const float*)d_in[3];
    const float* ad1w = (const float*)d_in[4];
    const float* b1   = (const float*)d_in[5];
    const float* W2   = (const float*)d_in[6];
    const float* as2w = (const float*)d_in[7];
    const float* ad2w = (const float*)d_in[8];
    const float* b2   = (const float*)d_in[9];

    int       n  = in_sizes[0] / CIN;
    long long E  = (long long)in_sizes[1] / 2;
    long long ET = E + n;

    unsigned *h1u, *h2u;
    float *ho1, *pad1, *pad2;
    int *deg, *off, *rank, *csr, *part;
    cudaGetSymbolAddress((void**)&h1u, g_h1u);
    cudaGetSymbolAddress((void**)&h2u, g_h2u);
    cudaGetSymbolAddress((void**)&ho1, g_ho1);
    cudaGetSymbolAddress((void**)&pad1, g_ad1);
    cudaGetSymbolAddress((void**)&pad2, g_ad2);
    cudaGetSymbolAddress((void**)&deg, g_deg);
    cudaGetSymbolAddress((void**)&off, g_off);
    cudaGetSymbolAddress((void**)&rank, g_rank);
    cudaGetSymbolAddress((void**)&csr, g_csr);
    cudaGetSymbolAddress((void**)&part, g_part);

    int nodeBlocks = (n + 127) / 128;                  // 782
    int aggBlocks  = (n * 32 + 255) / 256;
    int scanBlocks = (n + SCAN_CHUNK - 1) / SCAN_CHUNK;   // 98 (wave-1 resident)

    long long nh2  = (long long)n * H2;
    long long tail = (long long)out_size - nh2;
    bool castTail  = (tail == 2 * E);
    bool copyTail  = (tail == 4 * E);

    int CB  = (int)((E + 511) / 512);                  // count region (4 edges/thread)
    int EIB = castTail ? (int)((2 * E + 511) / 512) : 0;
    int SB  = (int)((E + 1023) / 1024);                // scatter real-edge blocks
    int SLB = (n + 1023) / 1024;                       // scatter self-loop blocks

    // ---- k1: dtype probe + flag clears + deg init ----
    init_k<<<1 + nodeBlocks, 128>>>((const uint2*)ei, 2 * E, deg, part, n);

    // ---- k2: fused gemm1 | count+rank | ei-cast ----
    fused1_k<<<nodeBlocks + CB + EIB, 128>>>(x, W1, as1w, ad1w, n, h1u, pad1,
                                             ei, E, deg, rank, nodeBlocks, CB,
                                             (float*)d_out + nh2);
    if (copyTail) {
        cudaMemcpyAsync((char*)d_out + nh2 * sizeof(float), ei,
                        (size_t)(2 * E) * sizeof(long long), cudaMemcpyDeviceToDevice);
    }

    // ---- k3: merged scan + scatter (spin-wait handoff) ----
    scan_scatter_k<<<scanBlocks + SB + SLB, 256>>>(deg, part, off, n, (int)ET,
                                                   ei, E, rank, csr, scanBlocks, SB);

    // ---- k4: agg layer1 (now launch #4 -> profiled), then layer 2 ----
    agg1_k<<<aggBlocks, 256>>>(off, csr, pad1, h1u, b1, n, ho1);
    gemm2_k<<<nodeBlocks, 128>>>(ho1, W2, as2w, ad2w, n, h2u, pad2);
    agg2_k<<<aggBlocks, 256>>>(off, csr, pad2, h2u, b2, n, (float*)d_out);
}

// round 16
// speedup vs baseline: 1.0714x; 1.0714x over previous
#include <cuda_runtime.h>
#include <cuda_fp16.h>
#include <cstdint>

#define MAXN 100000
#define MAXE 3200000
#define CIN 128
#define H1 50
#define H1P 52            // fp32 row stride for ho1 (gemm2 input)
#define H2 40
#define H2P 44
#define NEG_SLOPE 0.2f
#define LOG2E 1.4426950408889634f
#define SCAN_CHUNK 1024
#define R1U 32            // layer1 h row: feat pairs 0..24, marker@25, zeros 26..31
#define R2U 24            // layer2 h row: feat pairs 0..19, marker@20, zeros 21..23

// -------- scratch (device globals; no runtime allocation allowed) ----------
__device__ unsigned g_h1u[(size_t)MAXN * R1U];
__device__ unsigned g_h2u[(size_t)MAXN * R2U];
__device__ float    g_ho1[(size_t)MAXN * H1P];
__device__ float    g_as1[MAXN], g_ad1[MAXN];   // pre-scaled by log2e
__device__ float    g_as2[MAXN], g_ad2[MAXN];
__device__ int      g_deg[MAXN + 4];
__device__ int      g_off[MAXN + 1];
__device__ int      g_rank[MAXE + 4];           // per-edge rank within its dst segment
__device__ int      g_part[1100];               // lookback mailboxes (0 = not ready)
__device__ int      g_csr[MAXE + MAXN];
__device__ int      g_is64;

// -------- f32x2 helpers (Blackwell packed fp32, PTX-only) --------
__device__ __forceinline__ unsigned long long splat2(float v) {
    unsigned long long r; unsigned b = __float_as_uint(v);
    asm("mov.b64 %0, {%1, %1};" : "=l"(r) : "r"(b));
    return r;
}
__device__ __forceinline__ void ffma2(unsigned long long& acc, unsigned long long a, unsigned long long b) {
    asm("fma.rn.f32x2 %0, %1, %2, %0;" : "+l"(acc) : "l"(a), "l"(b));
}
__device__ __forceinline__ float2 unpack2(unsigned long long v) {
    unsigned lo, hi;
    asm("mov.b64 {%0, %1}, %2;" : "=r"(lo), "=r"(hi) : "l"(v));
    return make_float2(__uint_as_float(lo), __uint_as_float(hi));
}

// marker half2(1.0, 0.0)
#define MARKER_U 0x00003C00u

// ---------------- k1: block 0 = dtype probe + mailbox clear; rest deg init --
__global__ void init_k(const uint2* __restrict__ ei8, long long twoE,
                       int* __restrict__ deg, int* __restrict__ part, int n) {
    if (blockIdx.x == 0) {
        __shared__ int anyHi;
        if (threadIdx.x == 0) anyHi = 0;
        __syncthreads();
        long long K = twoE < 1024 ? twoE : 1024;
        for (long long i = threadIdx.x; i < K; i += blockDim.x) {
            uint2 v = ei8[i];
            if (v.y != 0u) anyHi = 1;   // int32 data: high half = next index, ~never all-zero
        }
        __syncthreads();
        if (threadIdx.x == 0) g_is64 = anyHi ? 0 : 1;
        for (int i = threadIdx.x; i < 1100; i += blockDim.x) part[i] = 0;
    } else {
        int i = (blockIdx.x - 1) * 128 + threadIdx.x;
        if (i < n) deg[i] = 1;          // slot 0 of each segment = self-loop
    }
}

// ---------------- k2 (fused): gemm1 | degree count+rank | ei-cast tail ------
__global__ void fused1_k(const float* __restrict__ x, const float* __restrict__ W,
                         const float* __restrict__ att_s, const float* __restrict__ att_d,
                         int n, unsigned* __restrict__ hrows,
                         float* __restrict__ as_o, float* __restrict__ ad_o,
                         const void* __restrict__ ei, long long E,
                         int* __restrict__ deg, int* __restrict__ rank,
                         int NB1, int CB, float* __restrict__ otail) {
    int bid = blockIdx.x;
    int tid = threadIdx.x;
    if (bid < NB1) {
        __shared__ float Ws[CIN * H1P];
        __shared__ float xs[128 * 17];
        __shared__ float sa[H1], sd[H1];
        for (int j = tid; j < CIN * H1; j += 128) {
            int k = j / H1, f = j - k * H1;
            Ws[k * H1P + f] = W[j];
        }
        if (tid < H1) { sa[tid] = att_s[tid]; sd[tid] = att_d[tid]; }

        int node = bid * 128 + tid;
        unsigned long long acc2[25];
#pragma unroll
        for (int i = 0; i < 25; i++) acc2[i] = 0ull;

        const float4* x4 = (const float4*)x;
        for (int k0 = 0; k0 < CIN; k0 += 16) {
            __syncthreads();
#pragma unroll
            for (int j = tid; j < 512; j += 128) {
                int nd = j >> 2, c = j & 3;
                int gn = bid * 128 + nd;
                float4 v = make_float4(0.f, 0.f, 0.f, 0.f);
                if (gn < n) v = x4[(size_t)gn * (CIN / 4) + (k0 >> 2) + c];
                float* p = &xs[nd * 17 + c * 4];
                p[0] = v.x; p[1] = v.y; p[2] = v.z; p[3] = v.w;
            }
            __syncthreads();
#pragma unroll
            for (int kk = 0; kk < 16; kk++) {
                unsigned long long xv2 = splat2(xs[tid * 17 + kk]);
                const unsigned long long* wr = (const unsigned long long*)&Ws[(k0 + kk) * H1P];
#pragma unroll
                for (int fp = 0; fp < 25; fp++) ffma2(acc2[fp], xv2, wr[fp]);
            }
        }
        if (node < n) {
            float s = 0.f, d = 0.f;
            unsigned* hr = hrows + (size_t)node * R1U;
#pragma unroll
            for (int fp = 0; fp < 25; fp++) {
                float2 v = unpack2(acc2[fp]);
                s += v.x * sa[2 * fp] + v.y * sa[2 * fp + 1];
                d += v.x * sd[2 * fp] + v.y * sd[2 * fp + 1];
                __half2 hh = __floats2half2_rn(v.x, v.y);
                hr[fp] = *(unsigned*)&hh;
            }
            hr[25] = MARKER_U;                  // z-marker: half2(1, 0)
#pragma unroll
            for (int q = 26; q < R1U; q++) hr[q] = 0u;
            as_o[node] = s * LOG2E;             // pre-scaled for exp2
            ad_o[node] = d * LOG2E;
        }
    } else if (bid < NB1 + CB) {
        // degree count + rank capture: 4 edges/thread
        long long i0 = (long long)(bid - NB1) * 512 + tid * 4;
        if (i0 < E) {
            int cnt = (E - i0 >= 4) ? 4 : (int)(E - i0);
            int d[4], rk[4];
            if (g_is64) {
                const long long* p = (const long long*)ei + E;   // dst row
                for (int u = 0; u < cnt; u++) d[u] = (int)p[i0 + u];
            } else {
                const int* p = (const int*)ei + E;
                if (cnt == 4) {
                    int4 q = *(const int4*)(p + i0);
                    d[0] = q.x; d[1] = q.y; d[2] = q.z; d[3] = q.w;
                } else {
                    for (int u = 0; u < cnt; u++) d[u] = p[i0 + u];
                }
            }
            for (int u = 0; u < cnt; u++) {
                int dd = d[u];
                if ((unsigned)dd >= (unsigned)n) dd = 0;
                rk[u] = atomicAdd(deg + dd, 1);              // rank >= 1 (0 = self-loop)
            }
            if (cnt == 4) *(int4*)(rank + i0) = make_int4(rk[0], rk[1], rk[2], rk[3]);
            else for (int u = 0; u < cnt; u++) rank[i0 + u] = rk[u];
        }
    } else {
        // ei-cast tail: 4 elems/thread
        long long twoE = 2 * E;
        long long j0 = (long long)(bid - NB1 - CB) * 512 + tid * 4;
        if (j0 < twoE) {
            float o[4]; int cnt = (twoE - j0 >= 4) ? 4 : (int)(twoE - j0);
            if (g_is64) {
                const long long* p = (const long long*)ei;
                for (int u = 0; u < cnt; u++) o[u] = (float)p[j0 + u];
            } else {
                const int* p = (const int*)ei;
                if (cnt == 4) {
                    int4 q = *(const int4*)(p + j0);
                    o[0] = (float)q.x; o[1] = (float)q.y; o[2] = (float)q.z; o[3] = (float)q.w;
                } else {
                    for (int u = 0; u < cnt; u++) o[u] = (float)p[j0 + u];
                }
            }
            if (cnt == 4) *(float4*)(otail + j0) = make_float4(o[0], o[1], o[2], o[3]);
            else for (int u = 0; u < cnt; u++) otail[j0 + u] = o[u];
        }
    }
}

// ---------------- single-kernel scan with decoupled lookback ----------------
__global__ void scan_k(const int* __restrict__ deg, int* __restrict__ part,
                       int* __restrict__ off, int n, int total) {
    __shared__ int ts[256];
    __shared__ int sbase;
    int b = blockIdx.x, t = threadIdx.x;
    int base = b * SCAN_CHUNK;
    int i0 = base + t * 4;
    int v0 = 0, v1 = 0, v2 = 0, v3 = 0;
    if (i0 + 3 < n) {
        int4 q = *(const int4*)(deg + i0);
        v0 = q.x; v1 = q.y; v2 = q.z; v3 = q.w;
    } else {
        if (i0 + 0 < n) v0 = deg[i0 + 0];
        if (i0 + 1 < n) v1 = deg[i0 + 1];
        if (i0 + 2 < n) v2 = deg[i0 + 2];
        if (i0 + 3 < n) v3 = deg[i0 + 3];
    }
    ts[t] = v0 + v1 + v2 + v3;
    __syncthreads();
#pragma unroll
    for (int d = 1; d < 256; d <<= 1) {
        int v = (t >= d) ? ts[t - d] : 0;
        __syncthreads();
        ts[t] += v;
        __syncthreads();
    }
    if (t == 0) atomicExch(part + b, ts[255]);   // chunk total >= 1
    if (t < 32) {
        int sum = 0;
        volatile int* vp = part;
        for (int i = t; i < b; i += 32) {
            int v;
            do { v = vp[i]; } while (v == 0);
            sum += v;
        }
#pragma unroll
        for (int o = 16; o > 0; o >>= 1) sum += __shfl_xor_sync(0xffffffffu, sum, o);
        if (t == 0) sbase = sum;
    }
    __syncthreads();
    int run = sbase + (t ? ts[t - 1] : 0);
    if (i0 + 0 < n) { off[i0 + 0] = run; run += v0; }
    if (i0 + 1 < n) { off[i0 + 1] = run; run += v1; }
    if (i0 + 2 < n) { off[i0 + 2] = run; run += v2; }
    if (i0 + 3 < n) { off[i0 + 3] = run; run += v3; }
    if (b == 0 && t == 0) off[n] = total;
}

// ---------------- scatter (atomic-free: pos = off[d] + rank) -----------------
__global__ void scatter_k(const void* __restrict__ ei, long long E, int n,
                          const int* __restrict__ off, const int* __restrict__ rank,
                          int* __restrict__ csr, int SB) {
    int bid = blockIdx.x, tid = threadIdx.x;
    if (bid < SB) {
        long long i0 = (long long)bid * 1024 + tid * 4;
        if (i0 >= E) return;
        int cnt = (E - i0 >= 4) ? 4 : (int)(E - i0);
        int s[4], d[4], rk[4];
        if (g_is64) {
            const long long* ps = (const long long*)ei;
            const long long* pd = ps + E;
            for (int u = 0; u < cnt; u++) { s[u] = (int)ps[i0 + u]; d[u] = (int)pd[i0 + u]; }
        } else {
            const int* ps = (const int*)ei;
            const int* pd = ps + E;
            if (cnt == 4) {
                int4 qs = *(const int4*)(ps + i0);
                int4 qd = *(const int4*)(pd + i0);
                s[0] = qs.x; s[1] = qs.y; s[2] = qs.z; s[3] = qs.w;
                d[0] = qd.x; d[1] = qd.y; d[2] = qd.z; d[3] = qd.w;
            } else {
                for (int u = 0; u < cnt; u++) { s[u] = ps[i0 + u]; d[u] = pd[i0 + u]; }
            }
        }
        if (cnt == 4) {
            int4 qr = *(const int4*)(rank + i0);
            rk[0] = qr.x; rk[1] = qr.y; rk[2] = qr.z; rk[3] = qr.w;
        } else {
            for (int u = 0; u < cnt; u++) rk[u] = rank[i0 + u];
        }
        for (int u = 0; u < cnt; u++) {
            int ss = s[u], dd = d[u];
            if ((unsigned)ss >= (unsigned)n) ss = 0;
            if ((unsigned)dd >= (unsigned)n) dd = 0;
            csr[off[dd] + rk[u]] = ss;
        }
    } else {
        int v0 = (bid - SB) * 1024 + tid * 4;
#pragma unroll
        for (int u = 0; u < 4; u++) {
            int v = v0 + u;
            if (v < n) csr[off[v]] = v;             // self-loop at slot 0
        }
    }
}

// ---------------- agg core: lane-parallel weights + marker-z -----------------
// weights for 8 edges computed in lanes 0..7 (each lane gathers as[] for its
// own edge); broadcast via 1 shfl per edge. z accumulates in the marker lane.
template <int STRIDE_U>
__device__ __forceinline__ void agg_core(const int* __restrict__ off, const int* __restrict__ csr,
                                         const float* __restrict__ as, const float* __restrict__ ad,
                                         const unsigned* __restrict__ hrows,
                                         int warp, int lane, float& ax, float& ay) {
    int beg = __ldg(off + warp), end = __ldg(off + warp + 1);
    float adv = __ldg(ad + warp);
    float adv2 = NEG_SLOPE * adv;
    ax = 0.f; ay = 0.f;
    bool ldok = (STRIDE_U == 32) || (lane < STRIDE_U);

    int p = beg;
    for (; p + 8 <= end; p += 8) {
        int sv = (lane < 8) ? __ldg(csr + p + lane) : 0;
        float asv = (lane < 8) ? __ldg(as + sv) : 0.f;     // per-lane weight gather
        float e1 = asv + adv;
        float e2 = fmaf(NEG_SLOPE, asv, adv2);
        float w = exp2f(fmaxf(e1, e2));                    // leaky+exp, 8 weights at once
        int s[8]; unsigned r[8];
#pragma unroll
        for (int u = 0; u < 8; u++) s[u] = __shfl_sync(0xffffffffu, sv, u);
#pragma unroll
        for (int u = 0; u < 8; u++)
            r[u] = ldok ? __ldg(hrows + (size_t)s[u] * STRIDE_U + lane) : 0u;
#pragma unroll
        for (int u = 0; u < 8; u++) {
            float wu = __shfl_sync(0xffffffffu, w, u);
            float2 hv = __half22float2(*(__half2*)&r[u]);
            ax += wu * hv.x; ay += wu * hv.y;              // marker lane: ax += wu
        }
    }
    for (; p < end; p++) {
        int s = __ldg(csr + p);
        float asv = __ldg(as + s);
        float e1 = asv + adv;
        float e2 = fmaf(NEG_SLOPE, asv, adv2);
        float w = exp2f(fmaxf(e1, e2));
        unsigned r = ldok ? __ldg(hrows + (size_t)s * STRIDE_U + lane) : 0u;
        float2 hv = __half22float2(*(__half2*)&r);
        ax += w * hv.x; ay += w * hv.y;
    }
}

// ---------------- agg layer1 -> fp32 ho1 rows --------------------------------
__global__ void agg1_k(const int* __restrict__ off, const int* __restrict__ csr,
                       const float* __restrict__ as, const float* __restrict__ ad,
                       const unsigned* __restrict__ hrows,
                       const float* __restrict__ bias, int n, float* __restrict__ out) {
    int warp = (blockIdx.x * blockDim.x + threadIdx.x) >> 5;
    int lane = threadIdx.x & 31;
    if (warp >= n) return;
    float ax, ay;
    agg_core<R1U>(off, csr, as, ad, hrows, warp, lane, ax, ay);
    float z = __shfl_sync(0xffffffffu, ax, 25);   // marker lane
    float inv = 1.f / z;
    if (lane < 25) {
        float2 b = __ldg((const float2*)bias + lane);
        float vx = ax * inv + b.x;
        float vy = ay * inv + b.y;
        float2 o;
        o.x = vx > 0.f ? vx : 0.f;
        o.y = vy > 0.f ? vy : 0.f;
        *(float2*)(out + (size_t)warp * H1P + 2 * lane) = o;
    }
}

// ---------------- GEMM2: h2 = ho1 @ W2 (50->40) -> fp16 rows ----------------
__global__ void gemm2_k(const float* __restrict__ hin, const float* __restrict__ W,
                        const float* __restrict__ att_s, const float* __restrict__ att_d,
                        int n, unsigned* __restrict__ hrows,
                        float* __restrict__ as_o, float* __restrict__ ad_o) {
    __shared__ float Ws[H1 * H2P];
    __shared__ float xs[128 * 53];
    __shared__ float sa[H2], sd[H2];
    int tid = threadIdx.x;
    for (int j = tid; j < H1 * H2; j += 128) {
        int k = j / H2, f = j - k * H2;
        Ws[k * H2P + f] = W[j];
    }
    if (tid < H2) { sa[tid] = att_s[tid]; sd[tid] = att_d[tid]; }

    const float4* hin4 = (const float4*)hin;
#pragma unroll
    for (int j = tid; j < 128 * 13; j += 128) {
        int nd = j / 13, q = j - nd * 13;
        int gn = blockIdx.x * 128 + nd;
        float4 v = make_float4(0.f, 0.f, 0.f, 0.f);
        if (gn < n) v = hin4[(size_t)gn * 13 + q];
        float* p = &xs[nd * 53 + q * 4];
        p[0] = v.x; p[1] = v.y; p[2] = v.z; p[3] = v.w;
    }
    __syncthreads();

    int node = blockIdx.x * 128 + tid;
    unsigned long long acc2[20];
#pragma unroll
    for (int i = 0; i < 20; i++) acc2[i] = 0ull;
#pragma unroll 2
    for (int k = 0; k < H1; k++) {
        unsigned long long xv2 = splat2(xs[tid * 53 + k]);
        const unsigned long long* wr = (const unsigned long long*)&Ws[k * H2P];
#pragma unroll
        for (int fp = 0; fp < 20; fp++) ffma2(acc2[fp], xv2, wr[fp]);
    }
    if (node < n) {
        float s = 0.f, d = 0.f;
        unsigned* hr = hrows + (size_t)node * R2U;
#pragma unroll
        for (int fp = 0; fp < 20; fp++) {
            float2 v = unpack2(acc2[fp]);
            s += v.x * sa[2 * fp] + v.y * sa[2 * fp + 1];
            d += v.x * sd[2 * fp] + v.y * sd[2 * fp + 1];
            __half2 hh = __floats2half2_rn(v.x, v.y);
            hr[fp] = *(unsigned*)&hh;
        }
        hr[20] = MARKER_U;                  // z-marker
        hr[21] = 0u; hr[22] = 0u; hr[23] = 0u;
        as_o[node] = s * LOG2E;
        ad_o[node] = d * LOG2E;
    }
}

// ---------------- agg layer2 -> d_out ----------------------------------------
__global__ void agg2_k(const int* __restrict__ off, const int* __restrict__ csr,
                       const float* __restrict__ as, const float* __restrict__ ad,
                       const unsigned* __restrict__ hrows,
                       const float* __restrict__ bias, int n, float* __restrict__ out) {
    int warp = (blockIdx.x * blockDim.x + threadIdx.x) >> 5;
    int lane = threadIdx.x & 31;
    if (warp >= n) return;
    float ax, ay;
    agg_core<R2U>(off, csr, as, ad, hrows, warp, lane, ax, ay);
    float z = __shfl_sync(0xffffffffu, ax, 20);   // marker lane
    float inv = 1.f / z;
    if (lane < 20) {
        float2 b = __ldg((const float2*)bias + lane);
        float vx = ax * inv + b.x;
        float vy = ay * inv + b.y;
        float2 o;
        o.x = vx > 0.f ? vx : 0.f;
        o.y = vy > 0.f ? vy : 0.f;
        *(float2*)(out + (size_t)warp * H2 + 2 * lane) = o;
    }
}

extern "C" void kernel_launch(void* const* d_in, const int* in_sizes, int n_in,
                              void* d_out, int out_size) {
    const float* x    = (const float*)d_in[0];
    const void*  ei   = d_in[1];
    const float* W1   = (const float*)d_in[2];
    const float* as1w = (const float*)d_in[3];
    const float* ad1w = (const float*)d_in[4];
    const float* b1   = (const float*)d_in[5];
    const float* W2   = (const float*)d_in[6];
    const float* as2w = (const float*)d_in[7];
    const float* ad2w = (const float*)d_in[8];
    const float* b2   = (const float*)d_in[9];

    int       n  = in_sizes[0] / CIN;
    long long E  = (long long)in_sizes[1] / 2;
    long long ET = E + n;

    unsigned *h1u, *h2u;
    float *ho1, *pas1, *pad1, *pas2, *pad2;
    int *deg, *off, *rank, *csr, *part;
    cudaGetSymbolAddress((void**)&h1u, g_h1u);
    cudaGetSymbolAddress((void**)&h2u, g_h2u);
    cudaGetSymbolAddress((void**)&ho1, g_ho1);
    cudaGetSymbolAddress((void**)&pas1, g_as1);
    cudaGetSymbolAddress((void**)&pad1, g_ad1);
    cudaGetSymbolAddress((void**)&pas2, g_as2);
    cudaGetSymbolAddress((void**)&pad2, g_ad2);
    cudaGetSymbolAddress((void**)&deg, g_deg);
    cudaGetSymbolAddress((void**)&off, g_off);
    cudaGetSymbolAddress((void**)&rank, g_rank);
    cudaGetSymbolAddress((void**)&csr, g_csr);
    cudaGetSymbolAddress((void**)&part, g_part);

    int nodeBlocks = (n + 127) / 128;                  // 782
    int aggBlocks  = (n * 32 + 255) / 256;
    int scanBlocks = (n + SCAN_CHUNK - 1) / SCAN_CHUNK;   // 98

    long long nh2  = (long long)n * H2;
    long long tail = (long long)out_size - nh2;
    bool castTail  = (tail == 2 * E);
    bool copyTail  = (tail == 4 * E);

    int CB  = (int)((E + 511) / 512);                  // count region (4 edges/thread)
    int EIB = castTail ? (int)((2 * E + 511) / 512) : 0;
    int SB  = (int)((E + 1023) / 1024);                // scatter real-edge blocks
    int SLB = (n + 1023) / 1024;                       // scatter self-loop blocks

    // ---- k1: dtype probe + lookback-mailbox clear + deg init ----
    init_k<<<1 + nodeBlocks, 128>>>((const uint2*)ei, 2 * E, deg, part, n);

    // ---- k2: fused gemm1 | count+rank | ei-cast ----
    fused1_k<<<nodeBlocks + CB + EIB, 128>>>(x, W1, as1w, ad1w, n, h1u, pas1, pad1,
                                             ei, E, deg, rank, nodeBlocks, CB,
                                             (float*)d_out + nh2);
    if (copyTail) {
        cudaMemcpyAsync((char*)d_out + nh2 * sizeof(float), ei,
                        (size_t)(2 * E) * sizeof(long long), cudaMemcpyDeviceToDevice);
    }

    // ---- CSR offsets + atomic-free scatter ----
    scan_k<<<scanBlocks, 256>>>(deg, part, off, n, (int)ET);
    scatter_k<<<SB + SLB, 256>>>(ei, E, n, off, rank, csr, SB);

    // ---- layer 1 aggregation, layer 2 ----
    agg1_k<<<aggBlocks, 256>>>(off, csr, pas1, pad1, h1u, b1, n, ho1);
    gemm2_k<<<nodeBlocks, 128>>>(ho1, W2, as2w, ad2w, n, h2u, pas2, pad2);
    agg2_k<<<aggBlocks, 256>>>(off, csr, pas2, pad2, h2u, b2, n, (float*)d_out);
}